// round 6
// baseline (speedup 1.0000x reference)
#include <cuda_runtime.h>

// B=32, P=3, D=300, N=2048.  x,y: [B,P,D,N] fp32.
// out: [B, P*N, 3] = {cos, l2, l1} per (b,p,n) vector of length D (stride N).
//
// R5 shape (one thread <-> one full-D column, 3072x64 balanced grid) with
// per-thread MLP raised: explicit 10-wide unroll loads all 20 values into
// registers before computing (regs ~44, MLP_eff ~20 vs ~9 at regs=32),
// plus __ldcs streaming hint (zero reuse, 472MB >> L2).

#define D_DIM 300
#define D_STEP 10
#define N_DIM 2048
#define BP 96
#define THREADS 64

__global__ __launch_bounds__(THREADS)
void sim_measure_kernel(const float* __restrict__ x,
                        const float* __restrict__ y,
                        float* __restrict__ out)
{
    const int idx = blockIdx.x * THREADS + threadIdx.x;   // 0 .. BP*N-1
    const int n  = idx & (N_DIM - 1);
    const int bp = idx >> 11;                             // / 2048

    const float* __restrict__ xp = x + (size_t)bp * D_DIM * N_DIM + n;
    const float* __restrict__ yp = y + (size_t)bp * D_DIM * N_DIM + n;

    float dot = 0.f, xx = 0.f, yy = 0.f, dd = 0.f, l1 = 0.f;

    for (int d0 = 0; d0 < D_DIM; d0 += D_STEP) {
        float a[D_STEP], b[D_STEP];
        // batch all loads first -> ~20 LDGs in flight per thread
        #pragma unroll
        for (int i = 0; i < D_STEP; ++i)
            a[i] = __ldcs(xp + (size_t)i * N_DIM);
        #pragma unroll
        for (int i = 0; i < D_STEP; ++i)
            b[i] = __ldcs(yp + (size_t)i * N_DIM);

        #pragma unroll
        for (int i = 0; i < D_STEP; ++i) {
            const float av = a[i], bv = b[i];
            dot = fmaf(av, bv, dot);
            xx  = fmaf(av, av, xx);
            yy  = fmaf(bv, bv, yy);
            const float df = av - bv;
            dd  = fmaf(df, df, dd);
            l1 += fabsf(df);
        }
        xp += (size_t)D_STEP * N_DIM;
        yp += (size_t)D_STEP * N_DIM;
    }

    // out layout: [bp, n, 3]
    float* o = out + ((size_t)bp * N_DIM + n) * 3;
    o[0] = dot * rsqrtf(xx * yy);
    o[1] = sqrtf(dd);
    o[2] = l1;
}

extern "C" void kernel_launch(void* const* d_in, const int* in_sizes, int n_in,
                              void* d_out, int out_size)
{
    const float* x = (const float*)d_in[0];
    const float* y = (const float*)d_in[1];
    float* out = (float*)d_out;

    const int total_threads = BP * N_DIM;        // 196608
    const int blocks = total_threads / THREADS;  // 3072
    sim_measure_kernel<<<blocks, THREADS>>>(x, y, out);
}

// round 7
// speedup vs baseline: 1.0028x; 1.0028x over previous
#include <cuda_runtime.h>

// B=32, P=3, D=300, N=2048.  x,y: [B,P,D,N] fp32.
// out: [B, P*N, 3] = {cos, l2, l1} per (b,p,n) vector of length D (stride N).
//
// R5 shape (one thread <-> one full-D column, 3072x64 grid) + ping-pong
// double-buffered software pipeline: chunk c+1 loads issue before chunk c is
// consumed, forcing overlapping live ranges (ptxas collapsed the R6 flat
// batch back to regs=31 / MLP~9). Steady state: 20 LDGs in flight/thread.

#define D_DIM 300
#define CH 5                 // d-rows per chunk
#define NCHUNK (D_DIM / CH)  // 60
#define N_DIM 2048
#define BP 96
#define THREADS 64

#define LOAD_CHUNK(A_, B_, base)                                   \
    do {                                                           \
        const size_t _o = (size_t)(base) * N_DIM;                  \
        _Pragma("unroll")                                          \
        for (int _i = 0; _i < CH; ++_i) {                          \
            A_[_i] = __ldg(xp + _o + (size_t)_i * N_DIM);          \
            B_[_i] = __ldg(yp + _o + (size_t)_i * N_DIM);          \
        }                                                          \
    } while (0)

#define COMPUTE_CHUNK(A_, B_)                                      \
    do {                                                           \
        _Pragma("unroll")                                          \
        for (int _i = 0; _i < CH; ++_i) {                          \
            const float _a = A_[_i], _b = B_[_i];                  \
            dot = fmaf(_a, _b, dot);                               \
            xx  = fmaf(_a, _a, xx);                                \
            yy  = fmaf(_b, _b, yy);                                \
            const float _d = _a - _b;                              \
            dd  = fmaf(_d, _d, dd);                                \
            l1 += fabsf(_d);                                       \
        }                                                          \
    } while (0)

__global__ __launch_bounds__(THREADS)
void sim_measure_kernel(const float* __restrict__ x,
                        const float* __restrict__ y,
                        float* __restrict__ out)
{
    const int idx = blockIdx.x * THREADS + threadIdx.x;   // 0 .. BP*N-1
    const int n  = idx & (N_DIM - 1);
    const int bp = idx >> 11;                             // / 2048

    const float* __restrict__ xp = x + (size_t)bp * D_DIM * N_DIM + n;
    const float* __restrict__ yp = y + (size_t)bp * D_DIM * N_DIM + n;

    float dot = 0.f, xx = 0.f, yy = 0.f, dd = 0.f, l1 = 0.f;

    float a0[CH], b0[CH], a1[CH], b1[CH];

    LOAD_CHUNK(a0, b0, 0 * CH);
    LOAD_CHUNK(a1, b1, 1 * CH);

    #pragma unroll 1
    for (int c = 0; c + 3 < NCHUNK; c += 2) {
        COMPUTE_CHUNK(a0, b0);
        LOAD_CHUNK(a0, b0, (c + 2) * CH);
        COMPUTE_CHUNK(a1, b1);
        LOAD_CHUNK(a1, b1, (c + 3) * CH);
    }
    // loop covered chunks 0..57 computed, 58/59 loaded
    COMPUTE_CHUNK(a0, b0);
    COMPUTE_CHUNK(a1, b1);

    // out layout: [bp, n, 3]
    float* o = out + ((size_t)bp * N_DIM + n) * 3;
    o[0] = dot * rsqrtf(xx * yy);
    o[1] = sqrtf(dd);
    o[2] = l1;
}

extern "C" void kernel_launch(void* const* d_in, const int* in_sizes, int n_in,
                              void* d_out, int out_size)
{
    const float* x = (const float*)d_in[0];
    const float* y = (const float*)d_in[1];
    float* out = (float*)d_out;

    const int total_threads = BP * N_DIM;        // 196608
    const int blocks = total_threads / THREADS;  // 3072
    sim_measure_kernel<<<blocks, THREADS>>>(x, y, out);
}

// round 8
// speedup vs baseline: 1.0562x; 1.0532x over previous
#include <cuda_runtime.h>

// B=32, P=3, D=300, N=2048.  x,y: [B,P,D,N] fp32.
// out: [B, P*N, 3] = {cos, l2, l1} per (b,p,n) vector of length D (stride N).
//
// R5 champion shape (one thread <-> one full-D column, 3072x64 balanced grid,
// unroll 5) with ld.global.nc.L2::256B: each L2 miss pulls the full 256B
// slice-chunk, so the sibling 128B line (loaded later by the adjacent warp)
// L2-hits and DRAM sees one 256B burst per chunk instead of two temporally
// scattered 128B fetches. MLP/occupancy knobs proved exhausted (R6/R7 flat
// at ~75% DRAM); this targets DRAM-side pattern efficiency directly.

#define D_DIM 300
#define N_DIM 2048
#define BP 96
#define THREADS 64

__device__ __forceinline__ float ldg_l2_256(const float* p)
{
    float v;
    asm("ld.global.nc.L2::256B.f32 %0, [%1];" : "=f"(v) : "l"(p));
    return v;
}

__global__ __launch_bounds__(THREADS)
void sim_measure_kernel(const float* __restrict__ x,
                        const float* __restrict__ y,
                        float* __restrict__ out)
{
    const int idx = blockIdx.x * THREADS + threadIdx.x;   // 0 .. BP*N-1
    const int n  = idx & (N_DIM - 1);
    const int bp = idx >> 11;                             // / 2048

    const float* __restrict__ xp = x + (size_t)bp * D_DIM * N_DIM + n;
    const float* __restrict__ yp = y + (size_t)bp * D_DIM * N_DIM + n;

    float dot = 0.f, xx = 0.f, yy = 0.f, dd = 0.f, l1 = 0.f;

    #pragma unroll 5
    for (int d = 0; d < D_DIM; ++d) {
        const float av = ldg_l2_256(xp + (size_t)d * N_DIM);
        const float bv = ldg_l2_256(yp + (size_t)d * N_DIM);
        dot = fmaf(av, bv, dot);
        xx  = fmaf(av, av, xx);
        yy  = fmaf(bv, bv, yy);
        const float df = av - bv;
        dd  = fmaf(df, df, dd);
        l1 += fabsf(df);
    }

    // out layout: [bp, n, 3]
    float* o = out + ((size_t)bp * N_DIM + n) * 3;
    o[0] = dot * rsqrtf(xx * yy);
    o[1] = sqrtf(dd);
    o[2] = l1;
}

extern "C" void kernel_launch(void* const* d_in, const int* in_sizes, int n_in,
                              void* d_out, int out_size)
{
    const float* x = (const float*)d_in[0];
    const float* y = (const float*)d_in[1];
    float* out = (float*)d_out;

    const int total_threads = BP * N_DIM;        // 196608
    const int blocks = total_threads / THREADS;  // 3072
    sim_measure_kernel<<<blocks, THREADS>>>(x, y, out);
}